// round 8
// baseline (speedup 1.0000x reference)
#include <cuda_runtime.h>
#include <stdint.h>

#define MAXN 500000
#define NBINS 65536
#define MAXCAND 65536
#define SHCAP 2048

__device__ float    g_sims[MAXN];
__device__ unsigned g_hist[NBINS];
__device__ unsigned g_selHi;
__device__ unsigned g_candKey[MAXCAND];
__device__ unsigned g_candIdx[MAXCAND];
__device__ unsigned g_candCount;
__device__ unsigned g_arrive;
__device__ volatile unsigned g_release;

// packed f32x2 fma
#define FMA2(d, a, b, c) \
    asm("fma.rn.f32x2 %0, %1, %2, %3;" : "=l"(d) : "l"(a), "l"(b), "l"(c))
#define UNPACK2(lo, hi, v) \
    asm("mov.b64 {%0, %1}, %2;" : "=f"(lo), "=f"(hi) : "l"(v))

__device__ __forceinline__ unsigned f2k(float f) {
    unsigned u = __float_as_uint(f);
    return (u & 0x80000000u) ? ~u : (u | 0x80000000u);
}
__device__ __forceinline__ float k2f(unsigned k) {
    unsigned u = (k & 0x80000000u) ? (k & 0x7FFFFFFFu) : ~k;
    return __uint_as_float(u);
}

// hi16 scan by one block (256 threads): bucket of the K-th largest -> g_selHi
__device__ void scan_hi16(int K) {
    __shared__ unsigned part[256];
    __shared__ unsigned a[256];
    int t = threadIdx.x;
    int base = t * 256;
    unsigned s = 0;
    #pragma unroll 8
    for (int i = 0; i < 256; i++) s += g_hist[base + i];
    part[t] = s;
    a[255 - t] = s;
    __syncthreads();
    for (int off = 1; off < 256; off <<= 1) {
        unsigned x = (t >= off) ? a[t - off] : 0u;
        __syncthreads();
        if (t >= off) a[t] += x;
        __syncthreads();
    }
    unsigned suffix   = a[255 - t];
    unsigned above_ex = suffix - part[t];
    if (above_ex < (unsigned)K && suffix >= (unsigned)K) {
        unsigned above = above_ex;
        for (int i = 255; i >= 0; i--) {
            unsigned h = g_hist[base + i];
            if (above + h >= (unsigned)K) { g_selHi = (unsigned)(base + i); break; }
            above += h;
        }
    }
    __syncthreads();
}

// exact final selection by one block from the candidate list
__device__ void finalize(float* __restrict__ out, int K) {
    __shared__ unsigned sKey[SHCAP];
    __shared__ unsigned sIdx[SHCAP];
    __shared__ unsigned red[256];
    int t = threadIdx.x;
    unsigned m = g_candCount; if (m > MAXCAND) m = MAXCAND;

    if (m <= SHCAP) {
        for (unsigned j = t; j < m; j += 256) { sKey[j] = g_candKey[j]; sIdx[j] = g_candIdx[j]; }
        __syncthreads();
        for (unsigned e = t; e < m; e += 256) {
            unsigned mk = sKey[e], mi = sIdx[e];
            unsigned rank = 0;
            for (unsigned j = 0; j < m; j++) {
                unsigned k2 = sKey[j];
                rank += (k2 > mk) || (k2 == mk && sIdx[j] < mi);
            }
            if (rank < (unsigned)K) {
                out[rank]     = k2f(mk);
                out[K + rank] = (float)mi;
            }
        }
        __syncthreads();
        return;
    }
    // degenerate fallback: bitwise descend to exact Kth-largest key T
    unsigned T = 0;
    for (int bit = 31; bit >= 0; bit--) {
        unsigned cand = T | (1u << bit);
        unsigned c = 0;
        for (unsigned j = t; j < m; j += 256) c += (g_candKey[j] >= cand);
        red[t] = c;
        __syncthreads();
        for (int off = 128; off > 0; off >>= 1) {
            if (t < off) red[t] += red[t + off];
            __syncthreads();
        }
        if (red[0] >= (unsigned)K) T = cand;
        __syncthreads();
    }
    __shared__ unsigned sCnt;
    if (t == 0) sCnt = 0;
    __syncthreads();
    for (unsigned j = t; j < m; j += 256) {
        unsigned k = g_candKey[j];
        if (k > T) {
            unsigned p = atomicAdd(&sCnt, 1u);
            sKey[p] = k; sIdx[p] = g_candIdx[j];
        }
    }
    __syncthreads();
    unsigned g = sCnt;
    unsigned need = (unsigned)K - g;
    for (unsigned it = 0; it < need; it++) {
        unsigned mn = 0xFFFFFFFFu;
        for (unsigned j = t; j < m; j += 256)
            if (g_candKey[j] == T) { unsigned v = g_candIdx[j]; if (v < mn) mn = v; }
        red[t] = mn;
        __syncthreads();
        for (int off = 128; off > 0; off >>= 1) {
            if (t < off) red[t] = min(red[t], red[t + off]);
            __syncthreads();
        }
        unsigned w = red[0];
        if (t == 0) { sKey[g + it] = T; sIdx[g + it] = w; }
        __syncthreads();
        for (unsigned j = t; j < m; j += 256)
            if (g_candKey[j] == T && g_candIdx[j] == w) g_candKey[j] = 0u;
        __syncthreads();
    }
    if (t < K) {
        unsigned mk = sKey[t], mi = sIdx[t];
        unsigned rank = 0;
        for (int j = 0; j < K; j++) {
            unsigned k2 = sKey[j];
            rank += (k2 > mk) || (k2 == mk && sIdx[j] < mi);
        }
        out[rank]     = k2f(mk);
        out[K + rank] = (float)mi;
    }
    __syncthreads();
}

// ---------------------------------------------------------------------------
// THE kernel: persistent grid (G = 3*numSMs blocks, all co-resident).
// prologue(qinv) -> sims+hist -> bar1(last: selHi scan) -> collect+hist-zero
// -> bar2(last: finalize + counter reset)
__global__ void __launch_bounds__(256, 3) k_all_512(
        const ulonglong2* __restrict__ db, const float* __restrict__ q,
        int n, int K, float* __restrict__ out, int G) {
    __shared__ __align__(16) float sq[512];
    __shared__ float sQinv;
    __shared__ unsigned sOld;
    int t = threadIdx.x;

    // ---- prologue: stage q, per-block qinv (no cross-block dependency)
    float v0 = q[t], v1 = q[t + 256];
    sq[t] = v0; sq[t + 256] = v1;
    {
        float s = v0 * v0 + v1 * v1;
        #pragma unroll
        for (int o = 16; o; o >>= 1) s += __shfl_xor_sync(0xFFFFFFFFu, s, o);
        __shared__ float wr[8];
        if ((t & 31) == 0) wr[t >> 5] = s;
        __syncthreads();
        if (t == 0) {
            float tot = 0.f;
            #pragma unroll
            for (int i = 0; i < 8; i++) tot += wr[i];
            sQinv = 1.0f / fmaxf(sqrtf(tot), 1e-8f);
        }
        __syncthreads();
    }
    float qinv = sQinv;

    int lane  = t & 31;
    int warp  = (blockIdx.x * blockDim.x + t) >> 5;
    int nwarp = (G * 256) >> 5;
    const ulonglong2* sq2 = (const ulonglong2*)sq;

    ulonglong2 q0 = sq2[lane];
    ulonglong2 q1 = sq2[lane + 32];
    ulonglong2 q2 = sq2[lane + 64];
    ulonglong2 q3 = sq2[lane + 96];

    // ---- phase 1: sims + hi16 histogram
    for (int row = warp * 2; row < n; row += nwarp * 2) {
        const ulonglong2* p0 = db + (size_t)row * 128;
        bool two = (row + 1) < n;
        const ulonglong2* p1 = two ? (p0 + 128) : p0;

        ulonglong2 a0 = p0[lane];
        ulonglong2 a1 = p0[lane + 32];
        ulonglong2 a2 = p0[lane + 64];
        ulonglong2 a3 = p0[lane + 96];
        ulonglong2 b0 = p1[lane];
        ulonglong2 b1 = p1[lane + 32];
        ulonglong2 b2 = p1[lane + 64];
        ulonglong2 b3 = p1[lane + 96];

        unsigned long long d0 = 0, s0 = 0, d1 = 0, s1 = 0;
        FMA2(d0, a0.x, q0.x, d0); FMA2(s0, a0.x, a0.x, s0);
        FMA2(d0, a0.y, q0.y, d0); FMA2(s0, a0.y, a0.y, s0);
        FMA2(d0, a1.x, q1.x, d0); FMA2(s0, a1.x, a1.x, s0);
        FMA2(d0, a1.y, q1.y, d0); FMA2(s0, a1.y, a1.y, s0);
        FMA2(d0, a2.x, q2.x, d0); FMA2(s0, a2.x, a2.x, s0);
        FMA2(d0, a2.y, q2.y, d0); FMA2(s0, a2.y, a2.y, s0);
        FMA2(d0, a3.x, q3.x, d0); FMA2(s0, a3.x, a3.x, s0);
        FMA2(d0, a3.y, q3.y, d0); FMA2(s0, a3.y, a3.y, s0);
        FMA2(d1, b0.x, q0.x, d1); FMA2(s1, b0.x, b0.x, s1);
        FMA2(d1, b0.y, q0.y, d1); FMA2(s1, b0.y, b0.y, s1);
        FMA2(d1, b1.x, q1.x, d1); FMA2(s1, b1.x, b1.x, s1);
        FMA2(d1, b1.y, q1.y, d1); FMA2(s1, b1.y, b1.y, s1);
        FMA2(d1, b2.x, q2.x, d1); FMA2(s1, b2.x, b2.x, s1);
        FMA2(d1, b2.y, q2.y, d1); FMA2(s1, b2.y, b2.y, s1);
        FMA2(d1, b3.x, q3.x, d1); FMA2(s1, b3.x, b3.x, s1);
        FMA2(d1, b3.y, q3.y, d1); FMA2(s1, b3.y, b3.y, s1);

        float lo, hi;
        UNPACK2(lo, hi, d0); float dot0 = lo + hi;
        UNPACK2(lo, hi, s0); float ss0  = lo + hi;
        UNPACK2(lo, hi, d1); float dot1 = lo + hi;
        UNPACK2(lo, hi, s1); float ss1  = lo + hi;

        #pragma unroll
        for (int o = 16; o; o >>= 1) {
            dot0 += __shfl_xor_sync(0xFFFFFFFFu, dot0, o);
            ss0  += __shfl_xor_sync(0xFFFFFFFFu, ss0,  o);
            dot1 += __shfl_xor_sync(0xFFFFFFFFu, dot1, o);
            ss1  += __shfl_xor_sync(0xFFFFFFFFu, ss1,  o);
        }
        if (lane == 0) {
            float s = dot0 * qinv / fmaxf(sqrtf(ss0), 1e-8f);
            g_sims[row] = s;
            atomicAdd(&g_hist[f2k(s) >> 16], 1u);
        }
        if (lane == 1 && two) {
            float s = dot1 * qinv / fmaxf(sqrtf(ss1), 1e-8f);
            g_sims[row + 1] = s;
            atomicAdd(&g_hist[f2k(s) >> 16], 1u);
        }
    }

    // ---- barrier 1 (last arriver computes selHi, then releases)
    __syncthreads();
    if (t == 0) { __threadfence(); sOld = atomicAdd(&g_arrive, 1u); }
    __syncthreads();
    if (sOld == (unsigned)(G - 1)) {
        scan_hi16(K);
        if (t == 0) { __threadfence(); g_release = 1u; }
    }
    if (t == 0) { while (g_release < 1u) { } }
    __syncthreads();
    __threadfence();

    // ---- phase 2: collect candidates; concurrently re-zero hist for next run
    unsigned selHi = g_selHi;
    int gt = blockIdx.x * 256 + t;
    int nt = G * 256;
    for (int i = gt; i < n; i += nt) {
        unsigned k = f2k(g_sims[i]);
        if ((k >> 16) >= selHi) {
            unsigned p = atomicAdd(&g_candCount, 1u);
            if (p < MAXCAND) { g_candKey[p] = k; g_candIdx[p] = (unsigned)i; }
        }
    }
    for (int i = gt; i < NBINS; i += nt) g_hist[i] = 0;

    // ---- barrier 2 (last arriver finalizes and resets state)
    __syncthreads();
    if (t == 0) { __threadfence(); sOld = atomicAdd(&g_arrive, 1u); }
    __syncthreads();
    if (sOld == (unsigned)(2 * G - 1)) {
        __threadfence();
        finalize(out, K);
        if (t == 0) {
            g_candCount = 0;
            g_arrive = 0;
            g_release = 0;
        }
    }
}

// ---------------------------------------------------------------------------
// generic-d fallback, same persistent structure
__global__ void __launch_bounds__(256, 3) k_all_gen(
        const float* __restrict__ db, const float* __restrict__ q,
        int n, int d, int K, float* __restrict__ out, int G) {
    extern __shared__ float dsq[];
    __shared__ float sQinv;
    __shared__ unsigned sOld;
    __shared__ float wr[8];
    int t = threadIdx.x;
    float s = 0.f;
    for (int i = t; i < d; i += 256) { float v = q[i]; dsq[i] = v; s += v * v; }
    #pragma unroll
    for (int o = 16; o; o >>= 1) s += __shfl_xor_sync(0xFFFFFFFFu, s, o);
    if ((t & 31) == 0) wr[t >> 5] = s;
    __syncthreads();
    if (t == 0) {
        float tot = 0.f;
        #pragma unroll
        for (int i = 0; i < 8; i++) tot += wr[i];
        sQinv = 1.0f / fmaxf(sqrtf(tot), 1e-8f);
    }
    __syncthreads();
    float qinv = sQinv;

    int lane  = t & 31;
    int warp  = (blockIdx.x * 256 + t) >> 5;
    int nwarp = (G * 256) >> 5;
    for (int row = warp; row < n; row += nwarp) {
        const float* p = db + (size_t)row * d;
        float dot = 0.f, ss = 0.f;
        for (int j = lane; j < d; j += 32) {
            float v = p[j];
            dot += v * dsq[j];
            ss  += v * v;
        }
        #pragma unroll
        for (int o = 16; o; o >>= 1) {
            dot += __shfl_down_sync(0xFFFFFFFFu, dot, o);
            ss  += __shfl_down_sync(0xFFFFFFFFu, ss, o);
        }
        if (lane == 0) {
            float sv = dot * qinv / fmaxf(sqrtf(ss), 1e-8f);
            g_sims[row] = sv;
            atomicAdd(&g_hist[f2k(sv) >> 16], 1u);
        }
    }

    __syncthreads();
    if (t == 0) { __threadfence(); sOld = atomicAdd(&g_arrive, 1u); }
    __syncthreads();
    if (sOld == (unsigned)(G - 1)) {
        scan_hi16(K);
        if (t == 0) { __threadfence(); g_release = 1u; }
    }
    if (t == 0) { while (g_release < 1u) { } }
    __syncthreads();
    __threadfence();

    unsigned selHi = g_selHi;
    int gt = blockIdx.x * 256 + t;
    int nt = G * 256;
    for (int i = gt; i < n; i += nt) {
        unsigned k = f2k(g_sims[i]);
        if ((k >> 16) >= selHi) {
            unsigned p = atomicAdd(&g_candCount, 1u);
            if (p < MAXCAND) { g_candKey[p] = k; g_candIdx[p] = (unsigned)i; }
        }
    }
    for (int i = gt; i < NBINS; i += nt) g_hist[i] = 0;

    __syncthreads();
    if (t == 0) { __threadfence(); sOld = atomicAdd(&g_arrive, 1u); }
    __syncthreads();
    if (sOld == (unsigned)(2 * G - 1)) {
        __threadfence();
        finalize(out, K);
        if (t == 0) {
            g_candCount = 0;
            g_arrive = 0;
            g_release = 0;
        }
    }
}

// ---------------------------------------------------------------------------
extern "C" void kernel_launch(void* const* d_in, const int* in_sizes, int n_in,
                              void* d_out, int out_size) {
    const float* q  = (const float*)d_in[0];
    const float* db = (const float*)d_in[1];
    int d = in_sizes[0];
    int n = in_sizes[1] / d;
    if (n > MAXN) n = MAXN;
    int K = out_size / 2;

    int sms = 148;
    cudaDeviceGetAttribute(&sms, cudaDevAttrMultiProcessorCount, 0);
    int G = sms * 3;   // co-resident by __launch_bounds__(256,3)

    if (d == 512)
        k_all_512<<<G, 256>>>((const ulonglong2*)db, q, n, K, (float*)d_out, G);
    else
        k_all_gen<<<G, 256, d * sizeof(float)>>>(db, q, n, d, K, (float*)d_out, G);
}

// round 9
// speedup vs baseline: 1.0001x; 1.0001x over previous
#include <cuda_runtime.h>
#include <stdint.h>

#define MAXN 500000
#define NBINS 65536
#define MAXCAND 65536
#define SHCAP 2048
#define CHUNK 16

__device__ float    g_sims[MAXN];
__device__ unsigned g_hist[NBINS];
__device__ unsigned g_selHi;
__device__ unsigned g_candKey[MAXCAND];
__device__ unsigned g_candIdx[MAXCAND];
__device__ unsigned g_candCount;
__device__ unsigned g_arrive;
__device__ unsigned g_work;
__device__ volatile unsigned g_release;

// packed f32x2 fma
#define FMA2(d, a, b, c) \
    asm("fma.rn.f32x2 %0, %1, %2, %3;" : "=l"(d) : "l"(a), "l"(b), "l"(c))
#define UNPACK2(lo, hi, v) \
    asm("mov.b64 {%0, %1}, %2;" : "=f"(lo), "=f"(hi) : "l"(v))

__device__ __forceinline__ unsigned f2k(float f) {
    unsigned u = __float_as_uint(f);
    return (u & 0x80000000u) ? ~u : (u | 0x80000000u);
}
__device__ __forceinline__ float k2f(unsigned k) {
    unsigned u = (k & 0x80000000u) ? (k & 0x7FFFFFFFu) : ~k;
    return __uint_as_float(u);
}

// hi16 scan by one block (256 threads): bucket of the K-th largest -> g_selHi
__device__ void scan_hi16(int K) {
    __shared__ unsigned part[256];
    __shared__ unsigned a[256];
    int t = threadIdx.x;
    int base = t * 256;
    unsigned s = 0;
    #pragma unroll 8
    for (int i = 0; i < 256; i++) s += g_hist[base + i];
    part[t] = s;
    a[255 - t] = s;
    __syncthreads();
    for (int off = 1; off < 256; off <<= 1) {
        unsigned x = (t >= off) ? a[t - off] : 0u;
        __syncthreads();
        if (t >= off) a[t] += x;
        __syncthreads();
    }
    unsigned suffix   = a[255 - t];
    unsigned above_ex = suffix - part[t];
    if (above_ex < (unsigned)K && suffix >= (unsigned)K) {
        unsigned above = above_ex;
        for (int i = 255; i >= 0; i--) {
            unsigned h = g_hist[base + i];
            if (above + h >= (unsigned)K) { g_selHi = (unsigned)(base + i); break; }
            above += h;
        }
    }
    __syncthreads();
}

// exact final selection by one block from the candidate list
__device__ void finalize(float* __restrict__ out, int K) {
    __shared__ unsigned sKey[SHCAP];
    __shared__ unsigned sIdx[SHCAP];
    __shared__ unsigned red[256];
    int t = threadIdx.x;
    unsigned m = g_candCount; if (m > MAXCAND) m = MAXCAND;

    if (m <= SHCAP) {
        for (unsigned j = t; j < m; j += 256) { sKey[j] = g_candKey[j]; sIdx[j] = g_candIdx[j]; }
        __syncthreads();
        for (unsigned e = t; e < m; e += 256) {
            unsigned mk = sKey[e], mi = sIdx[e];
            unsigned rank = 0;
            for (unsigned j = 0; j < m; j++) {
                unsigned k2 = sKey[j];
                rank += (k2 > mk) || (k2 == mk && sIdx[j] < mi);
            }
            if (rank < (unsigned)K) {
                out[rank]     = k2f(mk);
                out[K + rank] = (float)mi;
            }
        }
        __syncthreads();
        return;
    }
    // degenerate fallback: bitwise descend to exact Kth-largest key T
    unsigned T = 0;
    for (int bit = 31; bit >= 0; bit--) {
        unsigned cand = T | (1u << bit);
        unsigned c = 0;
        for (unsigned j = t; j < m; j += 256) c += (g_candKey[j] >= cand);
        red[t] = c;
        __syncthreads();
        for (int off = 128; off > 0; off >>= 1) {
            if (t < off) red[t] += red[t + off];
            __syncthreads();
        }
        if (red[0] >= (unsigned)K) T = cand;
        __syncthreads();
    }
    __shared__ unsigned sCnt;
    if (t == 0) sCnt = 0;
    __syncthreads();
    for (unsigned j = t; j < m; j += 256) {
        unsigned k = g_candKey[j];
        if (k > T) {
            unsigned p = atomicAdd(&sCnt, 1u);
            sKey[p] = k; sIdx[p] = g_candIdx[j];
        }
    }
    __syncthreads();
    unsigned g = sCnt;
    unsigned need = (unsigned)K - g;
    for (unsigned it = 0; it < need; it++) {
        unsigned mn = 0xFFFFFFFFu;
        for (unsigned j = t; j < m; j += 256)
            if (g_candKey[j] == T) { unsigned v = g_candIdx[j]; if (v < mn) mn = v; }
        red[t] = mn;
        __syncthreads();
        for (int off = 128; off > 0; off >>= 1) {
            if (t < off) red[t] = min(red[t], red[t + off]);
            __syncthreads();
        }
        unsigned w = red[0];
        if (t == 0) { sKey[g + it] = T; sIdx[g + it] = w; }
        __syncthreads();
        for (unsigned j = t; j < m; j += 256)
            if (g_candKey[j] == T && g_candIdx[j] == w) g_candKey[j] = 0u;
        __syncthreads();
    }
    if (t < K) {
        unsigned mk = sKey[t], mi = sIdx[t];
        unsigned rank = 0;
        for (int j = 0; j < K; j++) {
            unsigned k2 = sKey[j];
            rank += (k2 > mk) || (k2 == mk && sIdx[j] < mi);
        }
        out[rank]     = k2f(mk);
        out[K + rank] = (float)mi;
    }
    __syncthreads();
}

// ---------------------------------------------------------------------------
// THE kernel: persistent grid (G = 3*numSMs blocks, all co-resident).
// prologue(qinv) -> sims+hist via per-warp WORK QUEUE -> bar1(last: selHi)
// -> collect+hist-zero -> bar2(last: finalize + state reset)
__global__ void __launch_bounds__(256, 3) k_all_512(
        const ulonglong2* __restrict__ db, const float* __restrict__ q,
        int n, int K, float* __restrict__ out, int G) {
    __shared__ __align__(16) float sq[512];
    __shared__ float sQinv;
    __shared__ unsigned sOld;
    int t = threadIdx.x;

    // ---- prologue: stage q, per-block qinv (no cross-block dependency)
    float v0 = q[t], v1 = q[t + 256];
    sq[t] = v0; sq[t + 256] = v1;
    {
        float s = v0 * v0 + v1 * v1;
        #pragma unroll
        for (int o = 16; o; o >>= 1) s += __shfl_xor_sync(0xFFFFFFFFu, s, o);
        __shared__ float wr[8];
        if ((t & 31) == 0) wr[t >> 5] = s;
        __syncthreads();
        if (t == 0) {
            float tot = 0.f;
            #pragma unroll
            for (int i = 0; i < 8; i++) tot += wr[i];
            sQinv = 1.0f / fmaxf(sqrtf(tot), 1e-8f);
        }
        __syncthreads();
    }
    float qinv = sQinv;

    int lane = t & 31;
    const ulonglong2* sq2 = (const ulonglong2*)sq;

    ulonglong2 q0 = sq2[lane];
    ulonglong2 q1 = sq2[lane + 32];
    ulonglong2 q2 = sq2[lane + 64];
    ulonglong2 q3 = sq2[lane + 96];

    // ---- phase 1: sims + hi16 histogram, per-warp dynamic chunks
    for (;;) {
        int base;
        if (lane == 0) base = (int)atomicAdd(&g_work, (unsigned)CHUNK);
        base = __shfl_sync(0xFFFFFFFFu, base, 0);
        if (base >= n) break;
        int lim = min(base + CHUNK, n);

        for (int row = base; row < lim; row += 2) {
            const ulonglong2* p0 = db + (size_t)row * 128;
            bool two = (row + 1) < lim;
            const ulonglong2* p1 = two ? (p0 + 128) : p0;

            ulonglong2 a0 = p0[lane];
            ulonglong2 a1 = p0[lane + 32];
            ulonglong2 a2 = p0[lane + 64];
            ulonglong2 a3 = p0[lane + 96];
            ulonglong2 b0 = p1[lane];
            ulonglong2 b1 = p1[lane + 32];
            ulonglong2 b2 = p1[lane + 64];
            ulonglong2 b3 = p1[lane + 96];

            unsigned long long d0 = 0, s0 = 0, d1 = 0, s1 = 0;
            FMA2(d0, a0.x, q0.x, d0); FMA2(s0, a0.x, a0.x, s0);
            FMA2(d0, a0.y, q0.y, d0); FMA2(s0, a0.y, a0.y, s0);
            FMA2(d0, a1.x, q1.x, d0); FMA2(s0, a1.x, a1.x, s0);
            FMA2(d0, a1.y, q1.y, d0); FMA2(s0, a1.y, a1.y, s0);
            FMA2(d0, a2.x, q2.x, d0); FMA2(s0, a2.x, a2.x, s0);
            FMA2(d0, a2.y, q2.y, d0); FMA2(s0, a2.y, a2.y, s0);
            FMA2(d0, a3.x, q3.x, d0); FMA2(s0, a3.x, a3.x, s0);
            FMA2(d0, a3.y, q3.y, d0); FMA2(s0, a3.y, a3.y, s0);
            FMA2(d1, b0.x, q0.x, d1); FMA2(s1, b0.x, b0.x, s1);
            FMA2(d1, b0.y, q0.y, d1); FMA2(s1, b0.y, b0.y, s1);
            FMA2(d1, b1.x, q1.x, d1); FMA2(s1, b1.x, b1.x, s1);
            FMA2(d1, b1.y, q1.y, d1); FMA2(s1, b1.y, b1.y, s1);
            FMA2(d1, b2.x, q2.x, d1); FMA2(s1, b2.x, b2.x, s1);
            FMA2(d1, b2.y, q2.y, d1); FMA2(s1, b2.y, b2.y, s1);
            FMA2(d1, b3.x, q3.x, d1); FMA2(s1, b3.x, b3.x, s1);
            FMA2(d1, b3.y, q3.y, d1); FMA2(s1, b3.y, b3.y, s1);

            float lo, hi;
            UNPACK2(lo, hi, d0); float dot0 = lo + hi;
            UNPACK2(lo, hi, s0); float ss0  = lo + hi;
            UNPACK2(lo, hi, d1); float dot1 = lo + hi;
            UNPACK2(lo, hi, s1); float ss1  = lo + hi;

            #pragma unroll
            for (int o = 16; o; o >>= 1) {
                dot0 += __shfl_xor_sync(0xFFFFFFFFu, dot0, o);
                ss0  += __shfl_xor_sync(0xFFFFFFFFu, ss0,  o);
                dot1 += __shfl_xor_sync(0xFFFFFFFFu, dot1, o);
                ss1  += __shfl_xor_sync(0xFFFFFFFFu, ss1,  o);
            }
            if (lane == 0) {
                float s = dot0 * qinv / fmaxf(sqrtf(ss0), 1e-8f);
                g_sims[row] = s;
                atomicAdd(&g_hist[f2k(s) >> 16], 1u);
            }
            if (lane == 1 && two) {
                float s = dot1 * qinv / fmaxf(sqrtf(ss1), 1e-8f);
                g_sims[row + 1] = s;
                atomicAdd(&g_hist[f2k(s) >> 16], 1u);
            }
        }
    }

    // ---- barrier 1 (last arriver computes selHi, then releases)
    __syncthreads();
    if (t == 0) { __threadfence(); sOld = atomicAdd(&g_arrive, 1u); }
    __syncthreads();
    if (sOld == (unsigned)(G - 1)) {
        scan_hi16(K);
        if (t == 0) { __threadfence(); g_release = 1u; }
    }
    if (t == 0) { while (g_release < 1u) { } }
    __syncthreads();
    __threadfence();

    // ---- phase 2: collect candidates; concurrently re-zero hist for next run
    unsigned selHi = g_selHi;
    int gt = blockIdx.x * 256 + t;
    int nt = G * 256;
    for (int i = gt; i < n; i += nt) {
        unsigned k = f2k(g_sims[i]);
        if ((k >> 16) >= selHi) {
            unsigned p = atomicAdd(&g_candCount, 1u);
            if (p < MAXCAND) { g_candKey[p] = k; g_candIdx[p] = (unsigned)i; }
        }
    }
    for (int i = gt; i < NBINS; i += nt) g_hist[i] = 0;

    // ---- barrier 2 (last arriver finalizes and resets state)
    __syncthreads();
    if (t == 0) { __threadfence(); sOld = atomicAdd(&g_arrive, 1u); }
    __syncthreads();
    if (sOld == (unsigned)(2 * G - 1)) {
        __threadfence();
        finalize(out, K);
        if (t == 0) {
            g_candCount = 0;
            g_arrive = 0;
            g_work = 0;
            g_release = 0;
        }
    }
}

// ---------------------------------------------------------------------------
// generic-d fallback, same persistent structure (per-warp queue, 1 row/grab*8)
__global__ void __launch_bounds__(256, 3) k_all_gen(
        const float* __restrict__ db, const float* __restrict__ q,
        int n, int d, int K, float* __restrict__ out, int G) {
    extern __shared__ float dsq[];
    __shared__ float sQinv;
    __shared__ unsigned sOld;
    __shared__ float wr[8];
    int t = threadIdx.x;
    float s = 0.f;
    for (int i = t; i < d; i += 256) { float v = q[i]; dsq[i] = v; s += v * v; }
    #pragma unroll
    for (int o = 16; o; o >>= 1) s += __shfl_xor_sync(0xFFFFFFFFu, s, o);
    if ((t & 31) == 0) wr[t >> 5] = s;
    __syncthreads();
    if (t == 0) {
        float tot = 0.f;
        #pragma unroll
        for (int i = 0; i < 8; i++) tot += wr[i];
        sQinv = 1.0f / fmaxf(sqrtf(tot), 1e-8f);
    }
    __syncthreads();
    float qinv = sQinv;

    int lane = t & 31;
    for (;;) {
        int base;
        if (lane == 0) base = (int)atomicAdd(&g_work, (unsigned)CHUNK);
        base = __shfl_sync(0xFFFFFFFFu, base, 0);
        if (base >= n) break;
        int lim = min(base + CHUNK, n);
        for (int row = base; row < lim; row++) {
            const float* p = db + (size_t)row * d;
            float dot = 0.f, ss = 0.f;
            for (int j = lane; j < d; j += 32) {
                float v = p[j];
                dot += v * dsq[j];
                ss  += v * v;
            }
            #pragma unroll
            for (int o = 16; o; o >>= 1) {
                dot += __shfl_down_sync(0xFFFFFFFFu, dot, o);
                ss  += __shfl_down_sync(0xFFFFFFFFu, ss, o);
            }
            if (lane == 0) {
                float sv = dot * qinv / fmaxf(sqrtf(ss), 1e-8f);
                g_sims[row] = sv;
                atomicAdd(&g_hist[f2k(sv) >> 16], 1u);
            }
        }
    }

    __syncthreads();
    if (t == 0) { __threadfence(); sOld = atomicAdd(&g_arrive, 1u); }
    __syncthreads();
    if (sOld == (unsigned)(G - 1)) {
        scan_hi16(K);
        if (t == 0) { __threadfence(); g_release = 1u; }
    }
    if (t == 0) { while (g_release < 1u) { } }
    __syncthreads();
    __threadfence();

    unsigned selHi = g_selHi;
    int gt = blockIdx.x * 256 + t;
    int nt = G * 256;
    for (int i = gt; i < n; i += nt) {
        unsigned k = f2k(g_sims[i]);
        if ((k >> 16) >= selHi) {
            unsigned p = atomicAdd(&g_candCount, 1u);
            if (p < MAXCAND) { g_candKey[p] = k; g_candIdx[p] = (unsigned)i; }
        }
    }
    for (int i = gt; i < NBINS; i += nt) g_hist[i] = 0;

    __syncthreads();
    if (t == 0) { __threadfence(); sOld = atomicAdd(&g_arrive, 1u); }
    __syncthreads();
    if (sOld == (unsigned)(2 * G - 1)) {
        __threadfence();
        finalize(out, K);
        if (t == 0) {
            g_candCount = 0;
            g_arrive = 0;
            g_work = 0;
            g_release = 0;
        }
    }
}

// ---------------------------------------------------------------------------
extern "C" void kernel_launch(void* const* d_in, const int* in_sizes, int n_in,
                              void* d_out, int out_size) {
    const float* q  = (const float*)d_in[0];
    const float* db = (const float*)d_in[1];
    int d = in_sizes[0];
    int n = in_sizes[1] / d;
    if (n > MAXN) n = MAXN;
    int K = out_size / 2;

    int sms = 148;
    cudaDeviceGetAttribute(&sms, cudaDevAttrMultiProcessorCount, 0);
    int G = sms * 3;   // co-resident by __launch_bounds__(256,3)

    if (d == 512)
        k_all_512<<<G, 256>>>((const ulonglong2*)db, q, n, K, (float*)d_out, G);
    else
        k_all_gen<<<G, 256, d * sizeof(float)>>>(db, q, n, d, K, (float*)d_out, G);
}

// round 10
// speedup vs baseline: 1.2280x; 1.2279x over previous
#include <cuda_runtime.h>
#include <stdint.h>

#define MAXN 500000
#define NBINS 65536
#define MAXCAND 65536
#define SHCAP 2048

__device__ float    g_sims[MAXN];
__device__ unsigned g_hist[NBINS];
__device__ unsigned g_selHi;
__device__ unsigned g_candKey[MAXCAND];
__device__ unsigned g_candIdx[MAXCAND];
__device__ unsigned g_candCount;
__device__ unsigned g_arrive;
__device__ unsigned g_work;
__device__ volatile unsigned g_release;

// packed f32x2 fma
#define FMA2(d, a, b, c) \
    asm("fma.rn.f32x2 %0, %1, %2, %3;" : "=l"(d) : "l"(a), "l"(b), "l"(c))
#define UNPACK2(lo, hi, v) \
    asm("mov.b64 {%0, %1}, %2;" : "=f"(lo), "=f"(hi) : "l"(v))

__device__ __forceinline__ unsigned f2k(float f) {
    unsigned u = __float_as_uint(f);
    return (u & 0x80000000u) ? ~u : (u | 0x80000000u);
}
__device__ __forceinline__ float k2f(unsigned k) {
    unsigned u = (k & 0x80000000u) ? (k & 0x7FFFFFFFu) : ~k;
    return __uint_as_float(u);
}

// ---------------------------------------------------------------------------
// Fully parallel hi16 scan by one block (256 threads): finds the hi16 bucket
// containing the K-th largest key -> g_selHi. Two shared suffix-scans, no
// serial per-bin loop.
__device__ void scan_hi16(int K) {
    __shared__ unsigned part[256];
    __shared__ unsigned a[256];
    __shared__ int sWin;
    __shared__ unsigned sAbove;
    int t = threadIdx.x;

    // per-thread sum of 256 bins via 64 uint4 loads (high MLP)
    const uint4* h4 = (const uint4*)g_hist;
    int b4 = t * 64;
    unsigned s = 0;
    #pragma unroll 16
    for (int i = 0; i < 64; i++) {
        uint4 v = h4[b4 + i];
        s += v.x + v.y + v.z + v.w;
    }
    part[t] = s;
    a[255 - t] = s;        // reversed for suffix scan
    __syncthreads();
    for (int off = 1; off < 256; off <<= 1) {
        unsigned x = (t >= off) ? a[t - off] : 0u;
        __syncthreads();
        if (t >= off) a[t] += x;
        __syncthreads();
    }
    unsigned suffix   = a[255 - t];
    unsigned above_ex = suffix - part[t];
    if (above_ex < (unsigned)K && suffix >= (unsigned)K) { sWin = t; sAbove = above_ex; }
    __syncthreads();

    // within winning chunk: 256 bins, suffix scan by all threads
    int tw = sWin;
    unsigned Kt = (unsigned)K - sAbove;
    unsigned h = g_hist[tw * 256 + t];
    a[255 - t] = h;
    __syncthreads();
    for (int off = 1; off < 256; off <<= 1) {
        unsigned x = (t >= off) ? a[t - off] : 0u;
        __syncthreads();
        if (t >= off) a[t] += x;
        __syncthreads();
    }
    unsigned suf2   = a[255 - t];   // keys with bin >= t in chunk
    unsigned above2 = suf2 - h;     // keys with bin > t in chunk
    if (above2 < Kt && suf2 >= Kt) g_selHi = (unsigned)(tw * 256 + t);
    __syncthreads();
}

// ---------------------------------------------------------------------------
// exact final selection by one block from the candidate list
__device__ void finalize(float* __restrict__ out, int K) {
    __shared__ unsigned sKey[SHCAP];
    __shared__ unsigned sIdx[SHCAP];
    __shared__ unsigned red[256];
    int t = threadIdx.x;
    unsigned m = g_candCount; if (m > MAXCAND) m = MAXCAND;

    if (m <= SHCAP) {
        for (unsigned j = t; j < m; j += 256) { sKey[j] = g_candKey[j]; sIdx[j] = g_candIdx[j]; }
        __syncthreads();
        for (unsigned e = t; e < m; e += 256) {
            unsigned mk = sKey[e], mi = sIdx[e];
            unsigned rank = 0;
            for (unsigned j = 0; j < m; j++) {
                unsigned k2 = sKey[j];
                rank += (k2 > mk) || (k2 == mk && sIdx[j] < mi);
            }
            if (rank < (unsigned)K) {
                out[rank]     = k2f(mk);
                out[K + rank] = (float)mi;
            }
        }
        __syncthreads();
        return;
    }
    // degenerate fallback: bitwise descend to exact Kth-largest key T
    unsigned T = 0;
    for (int bit = 31; bit >= 0; bit--) {
        unsigned cand = T | (1u << bit);
        unsigned c = 0;
        for (unsigned j = t; j < m; j += 256) c += (g_candKey[j] >= cand);
        red[t] = c;
        __syncthreads();
        for (int off = 128; off > 0; off >>= 1) {
            if (t < off) red[t] += red[t + off];
            __syncthreads();
        }
        if (red[0] >= (unsigned)K) T = cand;
        __syncthreads();
    }
    __shared__ unsigned sCnt;
    if (t == 0) sCnt = 0;
    __syncthreads();
    for (unsigned j = t; j < m; j += 256) {
        unsigned k = g_candKey[j];
        if (k > T) {
            unsigned p = atomicAdd(&sCnt, 1u);
            sKey[p] = k; sIdx[p] = g_candIdx[j];
        }
    }
    __syncthreads();
    unsigned g = sCnt;
    unsigned need = (unsigned)K - g;
    for (unsigned it = 0; it < need; it++) {
        unsigned mn = 0xFFFFFFFFu;
        for (unsigned j = t; j < m; j += 256)
            if (g_candKey[j] == T) { unsigned v = g_candIdx[j]; if (v < mn) mn = v; }
        red[t] = mn;
        __syncthreads();
        for (int off = 128; off > 0; off >>= 1) {
            if (t < off) red[t] = min(red[t], red[t + off]);
            __syncthreads();
        }
        unsigned w = red[0];
        if (t == 0) { sKey[g + it] = T; sIdx[g + it] = w; }
        __syncthreads();
        for (unsigned j = t; j < m; j += 256)
            if (g_candKey[j] == T && g_candIdx[j] == w) g_candKey[j] = 0u;
        __syncthreads();
    }
    if (t < K) {
        unsigned mk = sKey[t], mi = sIdx[t];
        unsigned rank = 0;
        for (int j = 0; j < K; j++) {
            unsigned k2 = sKey[j];
            rank += (k2 > mk) || (k2 == mk && sIdx[j] < mi);
        }
        out[rank]     = k2f(mk);
        out[K + rank] = (float)mi;
    }
    __syncthreads();
}

// ---------------------------------------------------------------------------
// THE kernel: persistent grid (G = 3*numSMs blocks, all co-resident).
// prologue(qinv) -> sims+hist via GRADUATED work queue (16-row units, then
// 2-row tail units to kill barrier skew) -> bar1(last: parallel selHi scan)
// -> collect+hist-zero -> bar2(last: finalize + state reset)
__global__ void __launch_bounds__(256, 3) k_all_512(
        const ulonglong2* __restrict__ db, const float* __restrict__ q,
        int n, int K, float* __restrict__ out, int G,
        int nA, int uA) {
    __shared__ __align__(16) float sq[512];
    __shared__ float sQinv;
    __shared__ unsigned sOld;
    int t = threadIdx.x;

    // ---- prologue: stage q, per-block qinv (no cross-block dependency)
    float v0 = q[t], v1 = q[t + 256];
    sq[t] = v0; sq[t + 256] = v1;
    {
        float s = v0 * v0 + v1 * v1;
        #pragma unroll
        for (int o = 16; o; o >>= 1) s += __shfl_xor_sync(0xFFFFFFFFu, s, o);
        __shared__ float wr[8];
        if ((t & 31) == 0) wr[t >> 5] = s;
        __syncthreads();
        if (t == 0) {
            float tot = 0.f;
            #pragma unroll
            for (int i = 0; i < 8; i++) tot += wr[i];
            sQinv = 1.0f / fmaxf(sqrtf(tot), 1e-8f);
        }
        __syncthreads();
    }
    float qinv = sQinv;

    int lane = t & 31;
    const ulonglong2* sq2 = (const ulonglong2*)sq;

    ulonglong2 q0 = sq2[lane];
    ulonglong2 q1 = sq2[lane + 32];
    ulonglong2 q2 = sq2[lane + 64];
    ulonglong2 q3 = sq2[lane + 96];

    // ---- phase 1: sims + hi16 histogram, graduated work units
    for (;;) {
        int u;
        if (lane == 0) u = (int)atomicAdd(&g_work, 1u);
        u = __shfl_sync(0xFFFFFFFFu, u, 0);
        int rbase, rlim;
        if (u < uA) { rbase = u * 16; rlim = rbase + 16; }
        else        { rbase = nA + (u - uA) * 2; rlim = min(rbase + 2, n); }
        if (rbase >= n) break;

        for (int row = rbase; row < rlim; row += 2) {
            const ulonglong2* p0 = db + (size_t)row * 128;
            bool two = (row + 1) < rlim;
            const ulonglong2* p1 = two ? (p0 + 128) : p0;

            ulonglong2 a0 = p0[lane];
            ulonglong2 a1 = p0[lane + 32];
            ulonglong2 a2 = p0[lane + 64];
            ulonglong2 a3 = p0[lane + 96];
            ulonglong2 b0 = p1[lane];
            ulonglong2 b1 = p1[lane + 32];
            ulonglong2 b2 = p1[lane + 64];
            ulonglong2 b3 = p1[lane + 96];

            unsigned long long d0 = 0, s0 = 0, d1 = 0, s1 = 0;
            FMA2(d0, a0.x, q0.x, d0); FMA2(s0, a0.x, a0.x, s0);
            FMA2(d0, a0.y, q0.y, d0); FMA2(s0, a0.y, a0.y, s0);
            FMA2(d0, a1.x, q1.x, d0); FMA2(s0, a1.x, a1.x, s0);
            FMA2(d0, a1.y, q1.y, d0); FMA2(s0, a1.y, a1.y, s0);
            FMA2(d0, a2.x, q2.x, d0); FMA2(s0, a2.x, a2.x, s0);
            FMA2(d0, a2.y, q2.y, d0); FMA2(s0, a2.y, a2.y, s0);
            FMA2(d0, a3.x, q3.x, d0); FMA2(s0, a3.x, a3.x, s0);
            FMA2(d0, a3.y, q3.y, d0); FMA2(s0, a3.y, a3.y, s0);
            FMA2(d1, b0.x, q0.x, d1); FMA2(s1, b0.x, b0.x, s1);
            FMA2(d1, b0.y, q0.y, d1); FMA2(s1, b0.y, b0.y, s1);
            FMA2(d1, b1.x, q1.x, d1); FMA2(s1, b1.x, b1.x, s1);
            FMA2(d1, b1.y, q1.y, d1); FMA2(s1, b1.y, b1.y, s1);
            FMA2(d1, b2.x, q2.x, d1); FMA2(s1, b2.x, b2.x, s1);
            FMA2(d1, b2.y, q2.y, d1); FMA2(s1, b2.y, b2.y, s1);
            FMA2(d1, b3.x, q3.x, d1); FMA2(s1, b3.x, b3.x, s1);
            FMA2(d1, b3.y, q3.y, d1); FMA2(s1, b3.y, b3.y, s1);

            float lo, hi;
            UNPACK2(lo, hi, d0); float dot0 = lo + hi;
            UNPACK2(lo, hi, s0); float ss0  = lo + hi;
            UNPACK2(lo, hi, d1); float dot1 = lo + hi;
            UNPACK2(lo, hi, s1); float ss1  = lo + hi;

            #pragma unroll
            for (int o = 16; o; o >>= 1) {
                dot0 += __shfl_xor_sync(0xFFFFFFFFu, dot0, o);
                ss0  += __shfl_xor_sync(0xFFFFFFFFu, ss0,  o);
                dot1 += __shfl_xor_sync(0xFFFFFFFFu, dot1, o);
                ss1  += __shfl_xor_sync(0xFFFFFFFFu, ss1,  o);
            }
            if (lane == 0) {
                float s = dot0 * qinv / fmaxf(sqrtf(ss0), 1e-8f);
                g_sims[row] = s;
                atomicAdd(&g_hist[f2k(s) >> 16], 1u);
            }
            if (lane == 1 && two) {
                float s = dot1 * qinv / fmaxf(sqrtf(ss1), 1e-8f);
                g_sims[row + 1] = s;
                atomicAdd(&g_hist[f2k(s) >> 16], 1u);
            }
        }
    }

    // ---- barrier 1 (last arriver computes selHi, then releases)
    __syncthreads();
    if (t == 0) { __threadfence(); sOld = atomicAdd(&g_arrive, 1u); }
    __syncthreads();
    if (sOld == (unsigned)(G - 1)) {
        scan_hi16(K);
        if (t == 0) { __threadfence(); g_release = 1u; }
    }
    if (t == 0) { while (g_release < 1u) { } }
    __syncthreads();
    __threadfence();

    // ---- phase 2: collect candidates; concurrently re-zero hist for next run
    unsigned selHi = g_selHi;
    int gt = blockIdx.x * 256 + t;
    int nt = G * 256;
    for (int i = gt; i < n; i += nt) {
        unsigned k = f2k(g_sims[i]);
        if ((k >> 16) >= selHi) {
            unsigned p = atomicAdd(&g_candCount, 1u);
            if (p < MAXCAND) { g_candKey[p] = k; g_candIdx[p] = (unsigned)i; }
        }
    }
    for (int i = gt; i < NBINS; i += nt) g_hist[i] = 0;

    // ---- barrier 2 (last arriver finalizes and resets state)
    __syncthreads();
    if (t == 0) { __threadfence(); sOld = atomicAdd(&g_arrive, 1u); }
    __syncthreads();
    if (sOld == (unsigned)(2 * G - 1)) {
        __threadfence();
        finalize(out, K);
        if (t == 0) {
            g_candCount = 0;
            g_arrive = 0;
            g_work = 0;
            g_release = 0;
        }
    }
}

// ---------------------------------------------------------------------------
// generic-d fallback, same persistent structure (8-row units only)
__global__ void __launch_bounds__(256, 3) k_all_gen(
        const float* __restrict__ db, const float* __restrict__ q,
        int n, int d, int K, float* __restrict__ out, int G) {
    extern __shared__ float dsq[];
    __shared__ float sQinv;
    __shared__ unsigned sOld;
    __shared__ float wr[8];
    int t = threadIdx.x;
    float s = 0.f;
    for (int i = t; i < d; i += 256) { float v = q[i]; dsq[i] = v; s += v * v; }
    #pragma unroll
    for (int o = 16; o; o >>= 1) s += __shfl_xor_sync(0xFFFFFFFFu, s, o);
    if ((t & 31) == 0) wr[t >> 5] = s;
    __syncthreads();
    if (t == 0) {
        float tot = 0.f;
        #pragma unroll
        for (int i = 0; i < 8; i++) tot += wr[i];
        sQinv = 1.0f / fmaxf(sqrtf(tot), 1e-8f);
    }
    __syncthreads();
    float qinv = sQinv;

    int lane = t & 31;
    for (;;) {
        int base;
        if (lane == 0) base = (int)atomicAdd(&g_work, 8u);
        base = __shfl_sync(0xFFFFFFFFu, base, 0);
        if (base >= n) break;
        int lim = min(base + 8, n);
        for (int row = base; row < lim; row++) {
            const float* p = db + (size_t)row * d;
            float dot = 0.f, ss = 0.f;
            for (int j = lane; j < d; j += 32) {
                float v = p[j];
                dot += v * dsq[j];
                ss  += v * v;
            }
            #pragma unroll
            for (int o = 16; o; o >>= 1) {
                dot += __shfl_down_sync(0xFFFFFFFFu, dot, o);
                ss  += __shfl_down_sync(0xFFFFFFFFu, ss, o);
            }
            if (lane == 0) {
                float sv = dot * qinv / fmaxf(sqrtf(ss), 1e-8f);
                g_sims[row] = sv;
                atomicAdd(&g_hist[f2k(sv) >> 16], 1u);
            }
        }
    }

    __syncthreads();
    if (t == 0) { __threadfence(); sOld = atomicAdd(&g_arrive, 1u); }
    __syncthreads();
    if (sOld == (unsigned)(G - 1)) {
        scan_hi16(K);
        if (t == 0) { __threadfence(); g_release = 1u; }
    }
    if (t == 0) { while (g_release < 1u) { } }
    __syncthreads();
    __threadfence();

    unsigned selHi = g_selHi;
    int gt = blockIdx.x * 256 + t;
    int nt = G * 256;
    for (int i = gt; i < n; i += nt) {
        unsigned k = f2k(g_sims[i]);
        if ((k >> 16) >= selHi) {
            unsigned p = atomicAdd(&g_candCount, 1u);
            if (p < MAXCAND) { g_candKey[p] = k; g_candIdx[p] = (unsigned)i; }
        }
    }
    for (int i = gt; i < NBINS; i += nt) g_hist[i] = 0;

    __syncthreads();
    if (t == 0) { __threadfence(); sOld = atomicAdd(&g_arrive, 1u); }
    __syncthreads();
    if (sOld == (unsigned)(2 * G - 1)) {
        __threadfence();
        finalize(out, K);
        if (t == 0) {
            g_candCount = 0;
            g_arrive = 0;
            g_work = 0;
            g_release = 0;
        }
    }
}

// ---------------------------------------------------------------------------
extern "C" void kernel_launch(void* const* d_in, const int* in_sizes, int n_in,
                              void* d_out, int out_size) {
    const float* q  = (const float*)d_in[0];
    const float* db = (const float*)d_in[1];
    int d = in_sizes[0];
    int n = in_sizes[1] / d;
    if (n > MAXN) n = MAXN;
    int K = out_size / 2;

    int sms = 148;
    cudaDeviceGetAttribute(&sms, cudaDevAttrMultiProcessorCount, 0);
    int G = sms * 3;   // co-resident by __launch_bounds__(256,3)

    if (d == 512) {
        // graduated units: 16-row units over [0, nA), 2-row tail units over [nA, n)
        int nA = (n > 65536) ? ((n - 32768) & ~15) : 0;
        int uA = nA / 16;
        k_all_512<<<G, 256>>>((const ulonglong2*)db, q, n, K, (float*)d_out, G, nA, uA);
    } else {
        k_all_gen<<<G, 256, d * sizeof(float)>>>(db, q, n, d, K, (float*)d_out, G);
    }
}

// round 12
// speedup vs baseline: 1.2387x; 1.0087x over previous
#include <cuda_runtime.h>
#include <stdint.h>

#define MAXN 500000
#define NBINS 65536
#define MAXCAND 65536
#define SHCAP 2048

__device__ float    g_sims[MAXN];
__device__ unsigned g_hist[NBINS];
__device__ unsigned g_selHi;
__device__ unsigned g_candKey[MAXCAND];
__device__ unsigned g_candIdx[MAXCAND];
__device__ unsigned g_candCount;
__device__ unsigned g_arrive;
__device__ unsigned g_work;
__device__ volatile unsigned g_release;

// packed f32x2 fma
#define FMA2(d, a, b, c) \
    asm("fma.rn.f32x2 %0, %1, %2, %3;" : "=l"(d) : "l"(a), "l"(b), "l"(c))
#define UNPACK2(lo, hi, v) \
    asm("mov.b64 {%0, %1}, %2;" : "=f"(lo), "=f"(hi) : "l"(v))

__device__ __forceinline__ unsigned f2k(float f) {
    unsigned u = __float_as_uint(f);
    return (u & 0x80000000u) ? ~u : (u | 0x80000000u);
}
__device__ __forceinline__ float k2f(unsigned k) {
    unsigned u = (k & 0x80000000u) ? (k & 0x7FFFFFFFu) : ~k;
    return __uint_as_float(u);
}

// ---------------------------------------------------------------------------
// Fully parallel hi16 scan by one block (256 threads) -> g_selHi
__device__ void scan_hi16(int K) {
    __shared__ unsigned part[256];
    __shared__ unsigned a[256];
    __shared__ int sWin;
    __shared__ unsigned sAbove;
    int t = threadIdx.x;

    const uint4* h4 = (const uint4*)g_hist;
    int b4 = t * 64;
    unsigned s = 0;
    #pragma unroll 16
    for (int i = 0; i < 64; i++) {
        uint4 v = h4[b4 + i];
        s += v.x + v.y + v.z + v.w;
    }
    part[t] = s;
    a[255 - t] = s;
    __syncthreads();
    for (int off = 1; off < 256; off <<= 1) {
        unsigned x = (t >= off) ? a[t - off] : 0u;
        __syncthreads();
        if (t >= off) a[t] += x;
        __syncthreads();
    }
    unsigned suffix   = a[255 - t];
    unsigned above_ex = suffix - part[t];
    if (above_ex < (unsigned)K && suffix >= (unsigned)K) { sWin = t; sAbove = above_ex; }
    __syncthreads();

    int tw = sWin;
    unsigned Kt = (unsigned)K - sAbove;
    unsigned h = g_hist[tw * 256 + t];
    a[255 - t] = h;
    __syncthreads();
    for (int off = 1; off < 256; off <<= 1) {
        unsigned x = (t >= off) ? a[t - off] : 0u;
        __syncthreads();
        if (t >= off) a[t] += x;
        __syncthreads();
    }
    unsigned suf2   = a[255 - t];
    unsigned above2 = suf2 - h;
    if (above2 < Kt && suf2 >= Kt) g_selHi = (unsigned)(tw * 256 + t);
    __syncthreads();
}

// ---------------------------------------------------------------------------
// exact final selection by one block from the candidate list
__device__ void finalize(float* __restrict__ out, int K) {
    __shared__ unsigned sKey[SHCAP];
    __shared__ unsigned sIdx[SHCAP];
    __shared__ unsigned red[256];
    int t = threadIdx.x;
    unsigned m = g_candCount; if (m > MAXCAND) m = MAXCAND;

    if (m <= SHCAP) {
        for (unsigned j = t; j < m; j += 256) { sKey[j] = g_candKey[j]; sIdx[j] = g_candIdx[j]; }
        __syncthreads();
        for (unsigned e = t; e < m; e += 256) {
            unsigned mk = sKey[e], mi = sIdx[e];
            unsigned rank = 0;
            for (unsigned j = 0; j < m; j++) {
                unsigned k2 = sKey[j];
                rank += (k2 > mk) || (k2 == mk && sIdx[j] < mi);
            }
            if (rank < (unsigned)K) {
                out[rank]     = k2f(mk);
                out[K + rank] = (float)mi;
            }
        }
        __syncthreads();
        return;
    }
    unsigned T = 0;
    for (int bit = 31; bit >= 0; bit--) {
        unsigned cand = T | (1u << bit);
        unsigned c = 0;
        for (unsigned j = t; j < m; j += 256) c += (g_candKey[j] >= cand);
        red[t] = c;
        __syncthreads();
        for (int off = 128; off > 0; off >>= 1) {
            if (t < off) red[t] += red[t + off];
            __syncthreads();
        }
        if (red[0] >= (unsigned)K) T = cand;
        __syncthreads();
    }
    __shared__ unsigned sCnt;
    if (t == 0) sCnt = 0;
    __syncthreads();
    for (unsigned j = t; j < m; j += 256) {
        unsigned k = g_candKey[j];
        if (k > T) {
            unsigned p = atomicAdd(&sCnt, 1u);
            sKey[p] = k; sIdx[p] = g_candIdx[j];
        }
    }
    __syncthreads();
    unsigned g = sCnt;
    unsigned need = (unsigned)K - g;
    for (unsigned it = 0; it < need; it++) {
        unsigned mn = 0xFFFFFFFFu;
        for (unsigned j = t; j < m; j += 256)
            if (g_candKey[j] == T) { unsigned v = g_candIdx[j]; if (v < mn) mn = v; }
        red[t] = mn;
        __syncthreads();
        for (int off = 128; off > 0; off >>= 1) {
            if (t < off) red[t] = min(red[t], red[t + off]);
            __syncthreads();
        }
        unsigned w = red[0];
        if (t == 0) { sKey[g + it] = T; sIdx[g + it] = w; }
        __syncthreads();
        for (unsigned j = t; j < m; j += 256)
            if (g_candKey[j] == T && g_candIdx[j] == w) g_candKey[j] = 0u;
        __syncthreads();
    }
    if (t < K) {
        unsigned mk = sKey[t], mi = sIdx[t];
        unsigned rank = 0;
        for (int j = 0; j < K; j++) {
            unsigned k2 = sKey[j];
            rank += (k2 > mk) || (k2 == mk && sIdx[j] < mi);
        }
        out[rank]     = k2f(mk);
        out[K + rank] = (float)mi;
    }
    __syncthreads();
}

// ---------------------------------------------------------------------------
// THE kernel: persistent grid, geometric work units 16 -> 8 -> 4 rows.
// prologue(qinv) -> sims+hist -> bar1(last: parallel selHi scan)
// -> collect+hist-zero -> bar2(last: finalize + state reset)
__global__ void __launch_bounds__(256, 3) k_all_512(
        const ulonglong2* __restrict__ db, const float* __restrict__ q,
        int n, int K, float* __restrict__ out, int G,
        int u16, int r16end, int u8, int r8end) {
    __shared__ __align__(16) float sq[512];
    __shared__ float sQinv;
    __shared__ unsigned sOld;
    int t = threadIdx.x;

    // ---- prologue
    float v0 = q[t], v1 = q[t + 256];
    sq[t] = v0; sq[t + 256] = v1;
    {
        float s = v0 * v0 + v1 * v1;
        #pragma unroll
        for (int o = 16; o; o >>= 1) s += __shfl_xor_sync(0xFFFFFFFFu, s, o);
        __shared__ float wr[8];
        if ((t & 31) == 0) wr[t >> 5] = s;
        __syncthreads();
        if (t == 0) {
            float tot = 0.f;
            #pragma unroll
            for (int i = 0; i < 8; i++) tot += wr[i];
            sQinv = 1.0f / fmaxf(sqrtf(tot), 1e-8f);
        }
        __syncthreads();
    }
    float qinv = sQinv;

    int lane = t & 31;
    const ulonglong2* sq2 = (const ulonglong2*)sq;

    ulonglong2 q0 = sq2[lane];
    ulonglong2 q1 = sq2[lane + 32];
    ulonglong2 q2 = sq2[lane + 64];
    ulonglong2 q3 = sq2[lane + 96];

    // ---- phase 1: sims + hi16 histogram, geometric work units
    for (;;) {
        int u;
        if (lane == 0) u = (int)atomicAdd(&g_work, 1u);
        u = __shfl_sync(0xFFFFFFFFu, u, 0);
        int rbase, rlim;
        if (u < u16) {
            rbase = u * 16;                  rlim = rbase + 16;
        } else if (u < u16 + u8) {
            rbase = r16end + (u - u16) * 8;  rlim = rbase + 8;
        } else {
            rbase = r8end + (u - u16 - u8) * 4;
            rlim = min(rbase + 4, n);
        }
        if (rbase >= n) break;

        for (int row = rbase; row < rlim; row += 2) {
            const ulonglong2* p0 = db + (size_t)row * 128;
            bool two = (row + 1) < rlim;
            const ulonglong2* p1 = two ? (p0 + 128) : p0;

            ulonglong2 a0 = p0[lane];
            ulonglong2 a1 = p0[lane + 32];
            ulonglong2 a2 = p0[lane + 64];
            ulonglong2 a3 = p0[lane + 96];
            ulonglong2 b0 = p1[lane];
            ulonglong2 b1 = p1[lane + 32];
            ulonglong2 b2 = p1[lane + 64];
            ulonglong2 b3 = p1[lane + 96];

            unsigned long long d0 = 0, s0 = 0, d1 = 0, s1 = 0;
            FMA2(d0, a0.x, q0.x, d0); FMA2(s0, a0.x, a0.x, s0);
            FMA2(d0, a0.y, q0.y, d0); FMA2(s0, a0.y, a0.y, s0);
            FMA2(d0, a1.x, q1.x, d0); FMA2(s0, a1.x, a1.x, s0);
            FMA2(d0, a1.y, q1.y, d0); FMA2(s0, a1.y, a1.y, s0);
            FMA2(d0, a2.x, q2.x, d0); FMA2(s0, a2.x, a2.x, s0);
            FMA2(d0, a2.y, q2.y, d0); FMA2(s0, a2.y, a2.y, s0);
            FMA2(d0, a3.x, q3.x, d0); FMA2(s0, a3.x, a3.x, s0);
            FMA2(d0, a3.y, q3.y, d0); FMA2(s0, a3.y, a3.y, s0);
            FMA2(d1, b0.x, q0.x, d1); FMA2(s1, b0.x, b0.x, s1);
            FMA2(d1, b0.y, q0.y, d1); FMA2(s1, b0.y, b0.y, s1);
            FMA2(d1, b1.x, q1.x, d1); FMA2(s1, b1.x, b1.x, s1);
            FMA2(d1, b1.y, q1.y, d1); FMA2(s1, b1.y, b1.y, s1);
            FMA2(d1, b2.x, q2.x, d1); FMA2(s1, b2.x, b2.x, s1);
            FMA2(d1, b2.y, q2.y, d1); FMA2(s1, b2.y, b2.y, s1);
            FMA2(d1, b3.x, q3.x, d1); FMA2(s1, b3.x, b3.x, s1);
            FMA2(d1, b3.y, q3.y, d1); FMA2(s1, b3.y, b3.y, s1);

            float lo, hi;
            UNPACK2(lo, hi, d0); float dot0 = lo + hi;
            UNPACK2(lo, hi, s0); float ss0  = lo + hi;
            UNPACK2(lo, hi, d1); float dot1 = lo + hi;
            UNPACK2(lo, hi, s1); float ss1  = lo + hi;

            #pragma unroll
            for (int o = 16; o; o >>= 1) {
                dot0 += __shfl_xor_sync(0xFFFFFFFFu, dot0, o);
                ss0  += __shfl_xor_sync(0xFFFFFFFFu, ss0,  o);
                dot1 += __shfl_xor_sync(0xFFFFFFFFu, dot1, o);
                ss1  += __shfl_xor_sync(0xFFFFFFFFu, ss1,  o);
            }
            if (lane == 0) {
                float s = dot0 * qinv / fmaxf(sqrtf(ss0), 1e-8f);
                g_sims[row] = s;
                atomicAdd(&g_hist[f2k(s) >> 16], 1u);
            }
            if (lane == 1 && two) {
                float s = dot1 * qinv / fmaxf(sqrtf(ss1), 1e-8f);
                g_sims[row + 1] = s;
                atomicAdd(&g_hist[f2k(s) >> 16], 1u);
            }
        }
    }

    // ---- barrier 1 (last arriver computes selHi, then releases)
    __syncthreads();
    if (t == 0) { __threadfence(); sOld = atomicAdd(&g_arrive, 1u); }
    __syncthreads();
    if (sOld == (unsigned)(G - 1)) {
        scan_hi16(K);
        if (t == 0) { __threadfence(); g_release = 1u; }
    }
    if (t == 0) { while (g_release < 1u) { } }
    __syncthreads();
    __threadfence();

    // ---- phase 2: collect candidates; re-zero hist for next replay
    unsigned selHi = g_selHi;
    int gt = blockIdx.x * 256 + t;
    int nt = G * 256;
    for (int i = gt; i < n; i += nt) {
        unsigned k = f2k(g_sims[i]);
        if ((k >> 16) >= selHi) {
            unsigned p = atomicAdd(&g_candCount, 1u);
            if (p < MAXCAND) { g_candKey[p] = k; g_candIdx[p] = (unsigned)i; }
        }
    }
    for (int i = gt; i < NBINS; i += nt) g_hist[i] = 0;

    // ---- barrier 2 (last arriver finalizes and resets state)
    __syncthreads();
    if (t == 0) { __threadfence(); sOld = atomicAdd(&g_arrive, 1u); }
    __syncthreads();
    if (sOld == (unsigned)(2 * G - 1)) {
        __threadfence();
        finalize(out, K);
        if (t == 0) {
            g_candCount = 0;
            g_arrive = 0;
            g_work = 0;
            g_release = 0;
        }
    }
}

// ---------------------------------------------------------------------------
// generic-d fallback, same persistent structure (8-row units only)
__global__ void __launch_bounds__(256, 3) k_all_gen(
        const float* __restrict__ db, const float* __restrict__ q,
        int n, int d, int K, float* __restrict__ out, int G) {
    extern __shared__ float dsq[];
    __shared__ float sQinv;
    __shared__ unsigned sOld;
    __shared__ float wr[8];
    int t = threadIdx.x;
    float s = 0.f;
    for (int i = t; i < d; i += 256) { float v = q[i]; dsq[i] = v; s += v * v; }
    #pragma unroll
    for (int o = 16; o; o >>= 1) s += __shfl_xor_sync(0xFFFFFFFFu, s, o);
    if ((t & 31) == 0) wr[t >> 5] = s;
    __syncthreads();
    if (t == 0) {
        float tot = 0.f;
        #pragma unroll
        for (int i = 0; i < 8; i++) tot += wr[i];
        sQinv = 1.0f / fmaxf(sqrtf(tot), 1e-8f);
    }
    __syncthreads();
    float qinv = sQinv;

    int lane = t & 31;
    for (;;) {
        int base;
        if (lane == 0) base = (int)atomicAdd(&g_work, 8u);
        base = __shfl_sync(0xFFFFFFFFu, base, 0);
        if (base >= n) break;
        int lim = min(base + 8, n);
        for (int row = base; row < lim; row++) {
            const float* p = db + (size_t)row * d;
            float dot = 0.f, ss = 0.f;
            for (int j = lane; j < d; j += 32) {
                float v = p[j];
                dot += v * dsq[j];
                ss  += v * v;
            }
            #pragma unroll
            for (int o = 16; o; o >>= 1) {
                dot += __shfl_down_sync(0xFFFFFFFFu, dot, o);
                ss  += __shfl_down_sync(0xFFFFFFFFu, ss, o);
            }
            if (lane == 0) {
                float sv = dot * qinv / fmaxf(sqrtf(ss), 1e-8f);
                g_sims[row] = sv;
                atomicAdd(&g_hist[f2k(sv) >> 16], 1u);
            }
        }
    }

    __syncthreads();
    if (t == 0) { __threadfence(); sOld = atomicAdd(&g_arrive, 1u); }
    __syncthreads();
    if (sOld == (unsigned)(G - 1)) {
        scan_hi16(K);
        if (t == 0) { __threadfence(); g_release = 1u; }
    }
    if (t == 0) { while (g_release < 1u) { } }
    __syncthreads();
    __threadfence();

    unsigned selHi = g_selHi;
    int gt = blockIdx.x * 256 + t;
    int nt = G * 256;
    for (int i = gt; i < n; i += nt) {
        unsigned k = f2k(g_sims[i]);
        if ((k >> 16) >= selHi) {
            unsigned p = atomicAdd(&g_candCount, 1u);
            if (p < MAXCAND) { g_candKey[p] = k; g_candIdx[p] = (unsigned)i; }
        }
    }
    for (int i = gt; i < NBINS; i += nt) g_hist[i] = 0;

    __syncthreads();
    if (t == 0) { __threadfence(); sOld = atomicAdd(&g_arrive, 1u); }
    __syncthreads();
    if (sOld == (unsigned)(2 * G - 1)) {
        __threadfence();
        finalize(out, K);
        if (t == 0) {
            g_candCount = 0;
            g_arrive = 0;
            g_work = 0;
            g_release = 0;
        }
    }
}

// ---------------------------------------------------------------------------
extern "C" void kernel_launch(void* const* d_in, const int* in_sizes, int n_in,
                              void* d_out, int out_size) {
    const float* q  = (const float*)d_in[0];
    const float* db = (const float*)d_in[1];
    int d = in_sizes[0];
    int n = in_sizes[1] / d;
    if (n > MAXN) n = MAXN;
    int K = out_size / 2;

    int sms = 148;
    cudaDeviceGetAttribute(&sms, cudaDevAttrMultiProcessorCount, 0);
    int G = sms * 3;   // co-resident by __launch_bounds__(256,3)

    if (d == 512) {
        // geometric regimes: 16-row units until ~75k rows remain, 8-row until
        // ~42k remain, 4-row to the end. Each regime's span exceeds the
        // previous regime's single-unit duration -> straggler absorbed.
        int r16end = 0, r8end = 0, u16 = 0, u8 = 0;
        if (n > 120000) {
            r16end = ((n - 75000) / 16) * 16;
            u16 = r16end / 16;
            int rem = n - r16end;
            int span8 = (rem > 42000) ? ((rem - 42000) / 8) * 8 : 0;
            r8end = r16end + span8;
            u8 = span8 / 8;
        } else {
            r16end = 0; u16 = 0; r8end = 0; u8 = 0;  // all 4-row units
        }
        k_all_512<<<G, 256>>>((const ulonglong2*)db, q, n, K, (float*)d_out, G,
                              u16, r16end, u8, r8end);
    } else {
        k_all_gen<<<G, 256, d * sizeof(float)>>>(db, q, n, d, K, (float*)d_out, G);
    }
}